// round 8
// baseline (speedup 1.0000x reference)
#include <cuda_runtime.h>
#include <cuda_fp16.h>
#include <math.h>
#include <stdint.h>

// Problem shape
#define BB 8
#define TT 2048
#define CC 1024
#define HH 16
#define DD 64
#define MTOT (BB*TT)      // 16384
#define KDIM 1024
#define N_QKV 3072
#define N_PROJ 1024

// ---------------- scratch (__device__ globals; no allocation allowed) -------
__device__ float  g_qkv [(size_t)MTOT * N_QKV];   // phi_q | phi_k*m | v*m
__device__ __half g_xh  [(size_t)MTOT * KDIM];
__device__ __half g_wah [(size_t)N_QKV * KDIM];   // transposed [N,K], fp16
__device__ __half g_wph [(size_t)N_PROJ * KDIM];
__device__ __half g_yh  [(size_t)MTOT * CC];
__device__ float g_kvp[8 * BB*HH * DD*DD];
__device__ float g_ksp[8 * BB*HH * DD];
__device__ float g_kv [BB*HH * DD*DD];
__device__ float g_ks [BB*HH * DD];

// ---------------- helpers ----------------------------------------------------
__device__ __forceinline__ uint32_t smem_u32(const void* p) {
    uint32_t a;
    asm("{ .reg .u64 t; cvta.to.shared.u64 t, %1; cvt.u32.u64 %0, t; }"
        : "=r"(a) : "l"(p));
    return a;
}
__device__ __forceinline__ void cpasync16(uint32_t dst, const void* src) {
    asm volatile("cp.async.cg.shared.global [%0], [%1], 16;" :: "r"(dst), "l"(src));
}
#define CP_COMMIT() asm volatile("cp.async.commit_group;" ::: "memory")
#define CP_WAIT2()  asm volatile("cp.async.wait_group 2;" ::: "memory")

__device__ __forceinline__ void ldsm4(uint32_t (&r)[4], uint32_t addr) {
    asm volatile("ldmatrix.sync.aligned.m8n8.x4.shared.b16 {%0,%1,%2,%3}, [%4];"
                 : "=r"(r[0]), "=r"(r[1]), "=r"(r[2]), "=r"(r[3]) : "r"(addr));
}
__device__ __forceinline__ void mma16816(float (&c)[4], const uint32_t (&a)[4],
                                         uint32_t b0, uint32_t b1) {
    asm volatile(
        "mma.sync.aligned.m16n8k16.row.col.f32.f16.f16.f32 "
        "{%0,%1,%2,%3}, {%4,%5,%6,%7}, {%8,%9}, {%0,%1,%2,%3};"
        : "+f"(c[0]), "+f"(c[1]), "+f"(c[2]), "+f"(c[3])
        : "r"(a[0]), "r"(a[1]), "r"(a[2]), "r"(a[3]), "r"(b0), "r"(b1));
}

// FFMA-only exp(x) (no MUFU), rel err ~2.4e-6.
__device__ __forceinline__ float fexp(float x) {
    x = fmaxf(x, -80.f);
    float t = x * 1.4426950408889634f;
    float r = t + 12582912.0f;
    int   n = __float_as_int(r) - 0x4B400000;
    float f = t - (r - 12582912.0f);
    float g = f * 0.6931471805599453f;
    float p = fmaf(g, 0.008333333f, 0.041666667f);
    p = fmaf(g, p, 0.166666667f);
    p = fmaf(g, p, 0.5f);
    p = fmaf(g, p, 1.0f);
    p = fmaf(g, p, 1.0f);
    return __int_as_float(__float_as_int(p) + (n << 23));
}

// XOR-swizzled smem offset: 64B rows of 4x16B chunks; chunk ^= (row>>1)&3.
__device__ __forceinline__ uint32_t swz(int row, int ch) {
    return (uint32_t)((row << 6) + (((ch ^ (row >> 1)) & 3) << 4));
}

// ---------------- conversion kernels ----------------------------------------
__global__ __launch_bounds__(256)
void conv_x_kernel(const float4* __restrict__ in, uint2* __restrict__ hi) {
    size_t i = (size_t)blockIdx.x * blockDim.x + threadIdx.x;
    float4 v = in[i];
    __half h0 = __float2half(v.x), h1 = __float2half(v.y);
    __half h2 = __float2half(v.z), h3 = __float2half(v.w);
    uint32_t ha = (uint32_t)__half_as_ushort(h0) | ((uint32_t)__half_as_ushort(h1) << 16);
    uint32_t hb = (uint32_t)__half_as_ushort(h2) | ((uint32_t)__half_as_ushort(h3) << 16);
    hi[i] = make_uint2(ha, hb);
}

// w [K,N] row-major -> [N,K] (K-major), fp16
__global__ __launch_bounds__(256)
void transpose_h_kernel(const float* __restrict__ w, __half* __restrict__ hi,
                        int K, int N) {
    __shared__ float t[32][33];
    int n0 = blockIdx.x * 32, k0 = blockIdx.y * 32;
    int tx = threadIdx.x, ty = threadIdx.y;
#pragma unroll
    for (int i = 0; i < 4; i++)
        t[ty + i * 8][tx] = w[(size_t)(k0 + ty + i * 8) * N + n0 + tx];
    __syncthreads();
#pragma unroll
    for (int i = 0; i < 4; i++) {
        float v = t[tx][ty + i * 8];
        hi[(size_t)(n0 + ty + i * 8) * K + k0 + tx] = __float2half(v);
    }
}

// ---------------- mma.sync fp16 GEMM -----------------------------------------
// C[M,N] (fp32) = A[M,K] * B[N,K]^T + bias, fp16 operands, fp32 accumulate.
// Block: 128x128, BK=32, XOR-swizzled smem (16KB/stage), 4 buffers / depth-3
// prefetch, 8 warps (2x4), warp tile 64x32, 2 CTAs/SM.
#define BKG 32
#define OPB (128 * 64)          // 8192 B per operand tile
#define STGB (2 * OPB)          // 16384 B per stage (A|B)
#define NSTG 4
#define GSMEM (NSTG * STGB)     // 65536 B

template<int EPI>
__global__ __launch_bounds__(256, 2)
void mgemm(const __half* __restrict__ Ah, const __half* __restrict__ Bh,
           const float* __restrict__ bias, const int* __restrict__ am,
           float* __restrict__ Cout, int N)
{
    extern __shared__ char smem_raw[];
    const uint32_t sbase = smem_u32(smem_raw);
    const int tid = threadIdx.x;
    const int wid = tid >> 5, lane = tid & 31;
    const int warp_row = wid & 1;        // 0..1  (64 rows each)
    const int warp_col = wid >> 1;       // 0..3  (32 cols each)
    const int bm = blockIdx.y * 128;
    const int bn = blockIdx.x * 128;

    float acc[4][4][4];                  // [m-tile][n-tile][frag]
#pragma unroll
    for (int i = 0; i < 4; i++)
#pragma unroll
        for (int j = 0; j < 4; j++)
#pragma unroll
            for (int q = 0; q < 4; q++) acc[i][j][q] = 0.f;

    // stage loader: 128 rows x 4 chunks(16B) per operand; 2 rows/thread
    auto load_stage = [&](int s) {
        const int k0 = s * BKG;
        const uint32_t sb = sbase + (s % NSTG) * STGB;
#pragma unroll
        for (int i = 0; i < 2; i++) {
            int c = tid + i * 256;
            int row = c >> 2, ch = c & 3;
            uint32_t so = swz(row, ch);
            size_t ga = (size_t)(bm + row) * KDIM + k0 + ch * 8;
            size_t gb = (size_t)(bn + row) * KDIM + k0 + ch * 8;
            cpasync16(sb + 0 * OPB + so, Ah + ga);
            cpasync16(sb + 1 * OPB + so, Bh + gb);
        }
        CP_COMMIT();
    };

    const int NS = KDIM / BKG;   // 32
    load_stage(0); load_stage(1); load_stage(2);

    // per-lane ldmatrix fragment coordinates
    const int a_r = (lane & 7) + 8 * ((lane >> 3) & 1);   // row offset within 16
    const int a_k = 8 * (lane >> 4);                      // k offset 0/8
    const int b_r = (lane & 7) + 8 * (lane >> 4);         // n offset within 16
    const int b_k = 8 * ((lane >> 3) & 1);                // k offset 0/8

    for (int s = 0; s < NS; s++) {
        CP_WAIT2();
        __syncthreads();
        if (s + 3 < NS) load_stage(s + 3);

        const uint32_t sb = sbase + (s % NSTG) * STGB;

#pragma unroll
        for (int kk = 0; kk < 2; kk++) {
            uint32_t ah[4][4];
#pragma unroll
            for (int mi = 0; mi < 4; mi++) {
                int r = warp_row * 64 + mi * 16 + a_r;
                int ch = (kk * 16 + a_k) >> 3;
                ldsm4(ah[mi], sb + 0 * OPB + swz(r, ch));
            }
#pragma unroll
            for (int p = 0; p < 2; p++) {
                int rn = warp_col * 32 + p * 16 + b_r;
                int chb = (kk * 16 + b_k) >> 3;
                uint32_t bh[4];
                ldsm4(bh, sb + 1 * OPB + swz(rn, chb));
#pragma unroll
                for (int mi = 0; mi < 4; mi++)
#pragma unroll
                    for (int j = 0; j < 2; j++)
                        mma16816(acc[mi][2 * p + j], ah[mi], bh[2 * j], bh[2 * j + 1]);
            }
        }
    }

    // ---------------- epilogue ----------------
    const int er = lane >> 2;            // 0..7
    const int ec = (lane & 3) * 2;       // 0,2,4,6
#pragma unroll
    for (int mi = 0; mi < 4; mi++) {
#pragma unroll
        for (int half = 0; half < 2; half++) {
            int row = bm + warp_row * 64 + mi * 16 + er + half * 8;
            float mv = 1.f;
            if (EPI == 0) mv = (am[row] > 0) ? 1.f : 0.f;
#pragma unroll
            for (int ni = 0; ni < 4; ni++) {
                int col = bn + warp_col * 32 + ni * 8 + ec;
                float v0 = acc[mi][ni][2 * half]     + bias[col];
                float v1 = acc[mi][ni][2 * half + 1] + bias[col + 1];
                if (EPI == 0) {
                    if (col < 2048) {
                        v0 = (v0 > 0.f) ? (v0 + 1.f) : fexp(v0);   // elu + 1
                        v1 = (v1 > 0.f) ? (v1 + 1.f) : fexp(v1);
                    }
                    if (col >= 1024) { v0 *= mv; v1 *= mv; }
                }
                *(float2*)(Cout + (size_t)row * N + col) = make_float2(v0, v1);
            }
        }
    }
}

// ---------------- K2: per (b,h,chunk) partial kv / ksum ---------------------
__global__ __launch_bounds__(256)
void kv_partial(const float* __restrict__ qkv, float* __restrict__ kvp,
                float* __restrict__ ksp)
{
    __shared__ float ks[16][64];
    __shared__ float vs[16][64];

    const int bh = blockIdx.x >> 3;
    const int chn = blockIdx.x & 7;
    const int b = bh >> 4, h = bh & 15;
    const int tid = threadIdx.x;

    const float* kb = qkv + (size_t)b * TT * N_QKV + 1024 + h * DD;
    const float* vb = kb + 1024;

    const int lr  = tid >> 4;
    const int lc4 = (tid & 15) * 4;
    const int i0  = (tid >> 4) * 4;
    const int j0  = (tid & 15) * 4;

    float acc[4][4];
#pragma unroll
    for (int i = 0; i < 4; i++)
#pragma unroll
        for (int j = 0; j < 4; j++) acc[i][j] = 0.f;
    float ksum4[4] = {0.f, 0.f, 0.f, 0.f};
    const bool owns_ksum = ((tid & 15) == 0);

    const int tbeg = chn * (TT / 8);
    for (int t0 = tbeg; t0 < tbeg + TT / 8; t0 += 16) {
        size_t off = (size_t)(t0 + lr) * N_QKV + lc4;
        *(float4*)&ks[lr][lc4] = *(const float4*)(kb + off);
        *(float4*)&vs[lr][lc4] = *(const float4*)(vb + off);
        __syncthreads();
#pragma unroll
        for (int t = 0; t < 16; t++) {
            float4 k4 = *(float4*)&ks[t][i0];
            float4 v4 = *(float4*)&vs[t][j0];
            float ka[4] = {k4.x, k4.y, k4.z, k4.w};
            float va[4] = {v4.x, v4.y, v4.z, v4.w};
#pragma unroll
            for (int i = 0; i < 4; i++)
#pragma unroll
                for (int j = 0; j < 4; j++)
                    acc[i][j] = fmaf(ka[i], va[j], acc[i][j]);
            if (owns_ksum) {
#pragma unroll
                for (int i = 0; i < 4; i++) ksum4[i] += ka[i];
            }
        }
        __syncthreads();
    }

    float* kvdst = kvp + ((size_t)chn * 128 + bh) * DD * DD;
#pragma unroll
    for (int i = 0; i < 4; i++)
        *(float4*)&kvdst[(i0 + i) * DD + j0] =
            make_float4(acc[i][0], acc[i][1], acc[i][2], acc[i][3]);
    if (owns_ksum) {
#pragma unroll
        for (int i = 0; i < 4; i++)
            ksp[((size_t)chn * 128 + bh) * DD + i0 + i] = ksum4[i];
    }
}

__global__ __launch_bounds__(256)
void kv_reduce(const float* __restrict__ kvp, const float* __restrict__ ksp,
               float* __restrict__ kv, float* __restrict__ ks)
{
    const int bh = blockIdx.x;
    const int tid = threadIdx.x;
    for (int i = tid; i < DD * DD; i += 256) {
        float s = 0.f;
#pragma unroll
        for (int c = 0; c < 8; c++) s += kvp[((size_t)c * 128 + bh) * DD * DD + i];
        kv[(size_t)bh * DD * DD + i] = s;
    }
    if (tid < DD) {
        float s = 0.f;
#pragma unroll
        for (int c = 0; c < 8; c++) s += ksp[((size_t)c * 128 + bh) * DD + tid];
        ks[(size_t)bh * DD + tid] = s;
    }
}

// ---------------- K3: y = (phi_q . kv) / max(phi_q . ksum, eps) -> fp16 ------
__global__ __launch_bounds__(256)
void y_kernel(const float* __restrict__ qkv, const float* __restrict__ kv,
              const float* __restrict__ ksum, __half* __restrict__ yh)
{
    __shared__ float kvs[DD * DD];
    __shared__ float kss[DD];

    const int bh = blockIdx.y;
    const int b = bh >> 4, h = bh & 15;
    const int tid = threadIdx.x;

    const float4* kvsrc = (const float4*)(kv + (size_t)bh * DD * DD);
#pragma unroll
    for (int i = 0; i < 4; i++)
        ((float4*)kvs)[tid + i * 256] = kvsrc[tid + i * 256];
    if (tid < DD) kss[tid] = ksum[bh * DD + tid];
    __syncthreads();

    const int t = blockIdx.x * 128 + (tid >> 1);
    const int f0 = (tid & 1) * 32;
    const float* qrow = qkv + (size_t)(b * TT + t) * N_QKV + h * DD;

    float acc[32];
#pragma unroll
    for (int f = 0; f < 32; f++) acc[f] = 0.f;
    float den = 0.f;

#pragma unroll 4
    for (int d4 = 0; d4 < 16; d4++) {
        float4 q4 = *(const float4*)(qrow + d4 * 4);
        float qa[4] = {q4.x, q4.y, q4.z, q4.w};
#pragma unroll
        for (int u = 0; u < 4; u++) {
            int d = d4 * 4 + u;
            den = fmaf(qa[u], kss[d], den);
            const float* kr = &kvs[d * DD + f0];
#pragma unroll
            for (int f = 0; f < 32; f += 4) {
                float4 kv4 = *(const float4*)(kr + f);
                acc[f]     = fmaf(qa[u], kv4.x, acc[f]);
                acc[f + 1] = fmaf(qa[u], kv4.y, acc[f + 1]);
                acc[f + 2] = fmaf(qa[u], kv4.z, acc[f + 2]);
                acc[f + 3] = fmaf(qa[u], kv4.w, acc[f + 3]);
            }
        }
    }

    const float inv = 1.f / fmaxf(den, 1e-8f);
    const size_t off = (size_t)(b * TT + t) * CC + h * DD + f0;
#pragma unroll
    for (int f = 0; f < 32; f += 8) {
        uint32_t wh[4];
#pragma unroll
        for (int j = 0; j < 4; j++) {
            __half h0 = __float2half(acc[f + 2 * j]     * inv);
            __half h1 = __float2half(acc[f + 2 * j + 1] * inv);
            wh[j] = (uint32_t)__half_as_ushort(h0) | ((uint32_t)__half_as_ushort(h1) << 16);
        }
        *(uint4*)(yh + off + f) = make_uint4(wh[0], wh[1], wh[2], wh[3]);
    }
}

// ---------------------------------------------------------------------------
extern "C" void kernel_launch(void* const* d_in, const int* in_sizes, int n_in,
                              void* d_out, int out_size)
{
    const float* x      = (const float*)d_in[0];
    const int*   am     = (const int*)  d_in[1];
    const float* w_attn = (const float*)d_in[2];
    const float* b_attn = (const float*)d_in[3];
    const float* w_proj = (const float*)d_in[4];
    const float* b_proj = (const float*)d_in[5];
    float* out = (float*)d_out;

    float *qkv, *kvp, *ksp, *kvb, *ksb;
    __half *xh, *wah, *wph, *yh;
    cudaGetSymbolAddress((void**)&qkv, g_qkv);
    cudaGetSymbolAddress((void**)&xh,  g_xh);
    cudaGetSymbolAddress((void**)&wah, g_wah);
    cudaGetSymbolAddress((void**)&wph, g_wph);
    cudaGetSymbolAddress((void**)&yh,  g_yh);
    cudaGetSymbolAddress((void**)&kvp, g_kvp);
    cudaGetSymbolAddress((void**)&ksp, g_ksp);
    cudaGetSymbolAddress((void**)&kvb, g_kv);
    cudaGetSymbolAddress((void**)&ksb, g_ks);

    cudaFuncSetAttribute(mgemm<0>, cudaFuncAttributeMaxDynamicSharedMemorySize, GSMEM);
    cudaFuncSetAttribute(mgemm<1>, cudaFuncAttributeMaxDynamicSharedMemorySize, GSMEM);

    // fp16 conversions
    conv_x_kernel<<<(MTOT * KDIM / 4) / 256, 256>>>((const float4*)x, (uint2*)xh);
    transpose_h_kernel<<<dim3(N_QKV / 32, KDIM / 32), dim3(32, 8)>>>(w_attn, wah, KDIM, N_QKV);
    transpose_h_kernel<<<dim3(N_PROJ / 32, KDIM / 32), dim3(32, 8)>>>(w_proj, wph, KDIM, N_PROJ);

    // K1: qkv = x @ w_attn + b_attn (mma.sync fp16), fused phi/mask epilogue
    mgemm<0><<<dim3(N_QKV / 128, MTOT / 128), 256, GSMEM>>>(xh, wah, b_attn, am, qkv, N_QKV);
    // K2: per-head kv state + ksum (split over 8 T-chunks, then reduce)
    kv_partial<<<BB * HH * 8, 256>>>(qkv, kvp, ksp);
    kv_reduce<<<BB * HH, 256>>>(kvp, ksp, kvb, ksb);
    // K3: normalized linear attention output -> y (fp16)
    y_kernel<<<dim3(TT / 128, BB * HH), 256>>>(qkv, kvb, ksb, yh);
    // K4: out = y @ w_proj + b_proj (mma.sync fp16)
    mgemm<1><<<dim3(N_PROJ / 128, MTOT / 128), 256, GSMEM>>>(yh, wph, b_proj, nullptr, out, N_PROJ);
}